// round 1
// baseline (speedup 1.0000x reference)
#include <cuda_runtime.h>
#include <cuda_bf16.h>

#define NN 50000
#define EE 300000
#define ETOT (EE + NN)          // edges + self loops
#define NEG_SLOPE 0.2f
#define EPS 1e-16f
#define MINIT 0x007FFFFFu       // enc(-inf)

// ---------------- scratch (static device allocations only) ----------------
__device__ int g_src[ETOT];
__device__ int g_dst[ETOT];
__device__ int g_is64;

__device__ float g_h1[NN * 256];
__device__ float g_ssrc1[NN * 4];
__device__ float g_sdst1[NN * 4];
__device__ unsigned g_m1[NN * 4];
__device__ float g_z1[NN * 4];
__device__ float g_out1[NN * 256];

__device__ float g_h2[NN * 128];
__device__ float g_ssrc2[NN * 2];
__device__ float g_sdst2[NN * 2];
__device__ unsigned g_m2[NN * 2];
__device__ float g_z2[NN * 2];
__device__ float g_out2[NN * 128];

// order-preserving float <-> uint for atomicMax
__device__ __forceinline__ unsigned fenc(float f) {
    unsigned u = __float_as_uint(f);
    return (u & 0x80000000u) ? ~u : (u | 0x80000000u);
}
__device__ __forceinline__ float fdec(unsigned u) {
    return (u & 0x80000000u) ? __uint_as_float(u ^ 0x80000000u)
                             : __uint_as_float(~u);
}
__device__ __forceinline__ float lrelu(float x) {
    return x > 0.f ? x : NEG_SLOPE * x;
}
__device__ __forceinline__ float elu(float x) {
    return x > 0.f ? x : expm1f(x);
}

// ---------------- dtype detection + edge conversion ----------------
__global__ void k_detect(const int* ei32) {
    __shared__ int sflag;
    if (threadIdx.x == 0) sflag = 0;
    __syncthreads();
    int acc = 0;
    // first 2048 odd 32-bit words; 2*EE words exist even for int32 data
    for (int i = threadIdx.x; i < 2048; i += blockDim.x)
        acc |= ei32[2 * i + 1];
    if (acc) atomicOr(&sflag, 1);
    __syncthreads();
    if (threadIdx.x == 0) g_is64 = (sflag == 0) ? 1 : 0;
}

__global__ void k_convert(const void* ei) {
    int e = blockIdx.x * blockDim.x + threadIdx.x;
    if (e >= ETOT) return;
    if (e >= EE) {                      // self loops
        g_src[e] = e - EE;
        g_dst[e] = e - EE;
        return;
    }
    if (g_is64) {
        const long long* p = (const long long*)ei;
        g_src[e] = (int)p[e];
        g_dst[e] = (int)p[EE + e];
    } else {
        const int* p = (const int*)ei;
        g_src[e] = p[e];
        g_dst[e] = p[EE + e];
    }
}

// ---------------- init accumulators ----------------
__global__ void k_init() {
    int i = blockIdx.x * blockDim.x + threadIdx.x;
    int stride = gridDim.x * blockDim.x;
    for (int j = i; j < NN * 256; j += stride) g_out1[j] = 0.f;
    for (int j = i; j < NN * 128; j += stride) g_out2[j] = 0.f;
    for (int j = i; j < NN * 4; j += stride) { g_z1[j] = 0.f; g_m1[j] = MINIT; }
    for (int j = i; j < NN * 2; j += stride) { g_z2[j] = 0.f; g_m2[j] = MINIT; }
}

// ---------------- GEMM1: [50000,27] @ [27,256] ----------------
__global__ void k_gemm1(const float* __restrict__ x, const float* __restrict__ W1) {
    __shared__ float sW[27 * 256];
    __shared__ float sx[16 * 27];
    int tid = threadIdx.x;  // 256
    for (int i = tid; i < 27 * 256; i += 256) sW[i] = W1[i];
    int n0 = blockIdx.x * 16;  // 50000 = 3125 * 16 exactly
    for (int i = tid; i < 16 * 27; i += 256) sx[i] = x[n0 * 27 + i];
    __syncthreads();
    float acc[16];
#pragma unroll
    for (int m = 0; m < 16; m++) acc[m] = 0.f;
#pragma unroll
    for (int k = 0; k < 27; k++) {
        float w = sW[k * 256 + tid];
#pragma unroll
        for (int m = 0; m < 16; m++) acc[m] = fmaf(sx[m * 27 + k], w, acc[m]);
    }
#pragma unroll
    for (int m = 0; m < 16; m++) g_h1[(n0 + m) * 256 + tid] = acc[m];
}

// ---------------- per-node half scores ----------------
__global__ void k_scores1(const float* __restrict__ a_src, const float* __restrict__ a_dst) {
    int n = blockIdx.x;
    int warp = threadIdx.x >> 5, lane = threadIdx.x & 31;  // 4 warps = 4 heads
    const float* hp = g_h1 + n * 256 + warp * 64;
    float v0 = hp[lane], v1 = hp[lane + 32];
    float ps = v0 * a_src[warp * 64 + lane] + v1 * a_src[warp * 64 + lane + 32];
    float pd = v0 * a_dst[warp * 64 + lane] + v1 * a_dst[warp * 64 + lane + 32];
#pragma unroll
    for (int o = 16; o; o >>= 1) {
        ps += __shfl_down_sync(0xFFFFFFFFu, ps, o);
        pd += __shfl_down_sync(0xFFFFFFFFu, pd, o);
    }
    if (lane == 0) { g_ssrc1[n * 4 + warp] = ps; g_sdst1[n * 4 + warp] = pd; }
}

__global__ void k_scores2(const float* __restrict__ a_src, const float* __restrict__ a_dst) {
    int n = blockIdx.x;
    int warp = threadIdx.x >> 5, lane = threadIdx.x & 31;  // 2 warps = 2 heads
    const float* hp = g_h2 + n * 128 + warp * 64;
    float v0 = hp[lane], v1 = hp[lane + 32];
    float ps = v0 * a_src[warp * 64 + lane] + v1 * a_src[warp * 64 + lane + 32];
    float pd = v0 * a_dst[warp * 64 + lane] + v1 * a_dst[warp * 64 + lane + 32];
#pragma unroll
    for (int o = 16; o; o >>= 1) {
        ps += __shfl_down_sync(0xFFFFFFFFu, ps, o);
        pd += __shfl_down_sync(0xFFFFFFFFu, pd, o);
    }
    if (lane == 0) { g_ssrc2[n * 2 + warp] = ps; g_sdst2[n * 2 + warp] = pd; }
}

// ---------------- segment max over edges ----------------
__global__ void k_max1() {
    int e = blockIdx.x * blockDim.x + threadIdx.x;
    if (e >= ETOT) return;
    int s = g_src[e], d = g_dst[e];
    float4 ss = *(const float4*)(g_ssrc1 + s * 4);
    float4 sd = *(const float4*)(g_sdst1 + d * 4);
    atomicMax(&g_m1[d * 4 + 0], fenc(lrelu(ss.x + sd.x)));
    atomicMax(&g_m1[d * 4 + 1], fenc(lrelu(ss.y + sd.y)));
    atomicMax(&g_m1[d * 4 + 2], fenc(lrelu(ss.z + sd.z)));
    atomicMax(&g_m1[d * 4 + 3], fenc(lrelu(ss.w + sd.w)));
}

__global__ void k_max2() {
    int e = blockIdx.x * blockDim.x + threadIdx.x;
    if (e >= ETOT) return;
    int s = g_src[e], d = g_dst[e];
    float2 ss = *(const float2*)(g_ssrc2 + s * 2);
    float2 sd = *(const float2*)(g_sdst2 + d * 2);
    atomicMax(&g_m2[d * 2 + 0], fenc(lrelu(ss.x + sd.x)));
    atomicMax(&g_m2[d * 2 + 1], fenc(lrelu(ss.y + sd.y)));
}

// ---------------- fused exp + weighted scatter-aggregate ----------------
// one warp per edge
__global__ void k_agg1() {
    int widx = (blockIdx.x * blockDim.x + threadIdx.x) >> 5;
    if (widx >= ETOT) return;
    int lane = threadIdx.x & 31;
    int s = g_src[widx], d = g_dst[widx];
    float w = 0.f;
    if (lane < 4) {
        float l = lrelu(g_ssrc1[s * 4 + lane] + g_sdst1[d * 4 + lane]);
        float m = fdec(g_m1[d * 4 + lane]);
        w = expf(l - m);
        atomicAdd(&g_z1[d * 4 + lane], w);
    }
    float wh0 = __shfl_sync(0xFFFFFFFFu, w, 0);
    float wh1 = __shfl_sync(0xFFFFFFFFu, w, 1);
    float wh2 = __shfl_sync(0xFFFFFFFFu, w, 2);
    float wh3 = __shfl_sync(0xFFFFFFFFu, w, 3);
    const float* hp = g_h1 + (size_t)s * 256;
    float* op = g_out1 + (size_t)d * 256;
    float wj[8] = {wh0, wh0, wh1, wh1, wh2, wh2, wh3, wh3};
#pragma unroll
    for (int j = 0; j < 8; j++) {
        int c = lane + 32 * j;
        atomicAdd(&op[c], hp[c] * wj[j]);
    }
}

__global__ void k_agg2() {
    int widx = (blockIdx.x * blockDim.x + threadIdx.x) >> 5;
    if (widx >= ETOT) return;
    int lane = threadIdx.x & 31;
    int s = g_src[widx], d = g_dst[widx];
    float w = 0.f;
    if (lane < 2) {
        float l = lrelu(g_ssrc2[s * 2 + lane] + g_sdst2[d * 2 + lane]);
        float m = fdec(g_m2[d * 2 + lane]);
        w = expf(l - m);
        atomicAdd(&g_z2[d * 2 + lane], w);
    }
    float wh0 = __shfl_sync(0xFFFFFFFFu, w, 0);
    float wh1 = __shfl_sync(0xFFFFFFFFu, w, 1);
    const float* hp = g_h2 + (size_t)s * 128;
    float* op = g_out2 + (size_t)d * 128;
    float wj[4] = {wh0, wh0, wh1, wh1};
#pragma unroll
    for (int j = 0; j < 4; j++) {
        int c = lane + 32 * j;
        atomicAdd(&op[c], hp[c] * wj[j]);
    }
}

// ---------------- normalize + bias + ELU (layer 1, in place) ----------------
__global__ void k_norm1(const float* __restrict__ b1) {
    int n = blockIdx.x, c = threadIdx.x;  // 256 threads
    float z = g_z1[n * 4 + (c >> 6)] + EPS;
    float v = g_out1[(size_t)n * 256 + c] / z + b1[c];
    g_out1[(size_t)n * 256 + c] = elu(v);
}

// ---------------- GEMM2: [50000,256] @ [256,128] ----------------
__global__ void k_gemm2(const float* __restrict__ W2) {
    __shared__ float sx[32 * 256];  // 32 KB
    int tid = threadIdx.x;  // 128
    int n0 = blockIdx.x * 32;
    int cnt = min(32, NN - n0);
    const float* src = g_out1 + (size_t)n0 * 256;
    for (int i = tid; i < cnt * 256; i += 128) sx[i] = src[i];
    __syncthreads();
    float acc[32];
#pragma unroll
    for (int m = 0; m < 32; m++) acc[m] = 0.f;
    for (int k = 0; k < 256; k++) {
        float w = W2[k * 128 + tid];
#pragma unroll
        for (int m = 0; m < 32; m++) acc[m] = fmaf(sx[m * 256 + k], w, acc[m]);
    }
    for (int m = 0; m < cnt; m++) g_h2[(size_t)(n0 + m) * 128 + tid] = acc[m];
}

// ---------------- normalize + ELU + FC + sigmoid (layer 2) ----------------
__global__ void k_final(const float* __restrict__ b2, const float* __restrict__ Wfc,
                        const float* __restrict__ bfc, float* __restrict__ out) {
    int n = blockIdx.x, c = threadIdx.x;  // 128 threads
    int warp = c >> 5, lane = c & 31;
    float z = g_z2[n * 2 + (c >> 6)] + EPS;
    float v = g_out2[(size_t)n * 128 + c] / z + b2[c];
    v = elu(v);
    float t = v * Wfc[c];
#pragma unroll
    for (int o = 16; o; o >>= 1) t += __shfl_down_sync(0xFFFFFFFFu, t, o);
    __shared__ float sred[4];
    if (lane == 0) sred[warp] = t;
    __syncthreads();
    if (c == 0) {
        float s = sred[0] + sred[1] + sred[2] + sred[3] + bfc[0];
        out[n] = 1.f / (1.f + expf(-s));
    }
}

// ---------------- launch ----------------
extern "C" void kernel_launch(void* const* d_in, const int* in_sizes, int n_in,
                              void* d_out, int out_size) {
    const float* x      = (const float*)d_in[0];
    const void*  ei     = d_in[1];
    const float* W1     = (const float*)d_in[2];
    const float* a_src1 = (const float*)d_in[3];
    const float* a_dst1 = (const float*)d_in[4];
    const float* b1     = (const float*)d_in[5];
    const float* W2     = (const float*)d_in[6];
    const float* a_src2 = (const float*)d_in[7];
    const float* a_dst2 = (const float*)d_in[8];
    const float* b2     = (const float*)d_in[9];
    const float* Wfc    = (const float*)d_in[10];
    const float* bfc    = (const float*)d_in[11];
    float* out = (float*)d_out;

    k_detect<<<1, 256>>>((const int*)ei);
    k_convert<<<(ETOT + 255) / 256, 256>>>(ei);
    k_init<<<2048, 256>>>();

    // layer 1
    k_gemm1<<<NN / 16, 256>>>(x, W1);
    k_scores1<<<NN, 128>>>(a_src1, a_dst1);
    k_max1<<<(ETOT + 255) / 256, 256>>>();
    k_agg1<<<(ETOT + 7) / 8, 256>>>();   // 1 warp / edge, 8 warps / block
    k_norm1<<<NN, 256>>>(b1);

    // layer 2
    k_gemm2<<<(NN + 31) / 32, 128>>>(W2);
    k_scores2<<<NN, 64>>>(a_src2, a_dst2);
    k_max2<<<(ETOT + 255) / 256, 256>>>();
    k_agg2<<<(ETOT + 7) / 8, 256>>>();
    k_final<<<NN, 128>>>(b2, Wfc, bfc, out);
}

// round 3
// speedup vs baseline: 1.6896x; 1.6896x over previous
#include <cuda_runtime.h>
#include <cuda_bf16.h>

#define NN 50000
#define EE 300000
#define ETOT (EE + NN)          // edges + self loops
#define NEG_SLOPE 0.2f
#define EPS 1e-16f

typedef unsigned long long ull;

// ---------------- scratch (static device allocations only) ----------------
__device__ int g_src[ETOT];
__device__ int g_dst[ETOT];
__device__ int g_csr[ETOT];      // src ids sorted by dst
__device__ int g_deg[NN];
__device__ int g_rs[NN + 1];     // row starts
__device__ int g_cur[NN];        // scatter cursors
__device__ int g_is64;

__device__ float g_h1[NN * 256];
__device__ float g_ssrc1[NN * 4];
__device__ float g_sdst1[NN * 4];
__device__ float g_out1[NN * 256];   // layer-1 ELU output

__device__ float g_h2[NN * 128];
__device__ float g_ssrc2[NN * 2];
__device__ float g_sdst2[NN * 2];

// ---------------- helpers ----------------
__device__ __forceinline__ float lrelu(float x) {
    return x > 0.f ? x : NEG_SLOPE * x;
}
__device__ __forceinline__ float elu(float x) {
    return x > 0.f ? x : expm1f(x);
}
__device__ __forceinline__ ull pack2(float a, float b) {
    ull r; asm("mov.b64 %0,{%1,%2};" : "=l"(r) : "f"(a), "f"(b)); return r;
}
__device__ __forceinline__ void unpack2(ull p, float& a, float& b) {
    asm("mov.b64 {%0,%1},%2;" : "=f"(a), "=f"(b) : "l"(p));
}
__device__ __forceinline__ ull fma2(ull a, ull b, ull c) {
    ull d; asm("fma.rn.f32x2 %0,%1,%2,%3;" : "=l"(d) : "l"(a), "l"(b), "l"(c));
    return d;
}

// ---------------- prep: zero deg + dtype detect ----------------
__global__ void k_prep(const int* __restrict__ ei32) {
    int i = blockIdx.x * blockDim.x + threadIdx.x;
    for (int j = i; j < NN; j += gridDim.x * blockDim.x) g_deg[j] = 0;
    if (blockIdx.x == 0) {
        __shared__ int sflag;
        if (threadIdx.x == 0) sflag = 0;
        __syncthreads();
        int acc = 0;
        for (int j = threadIdx.x; j < 2048; j += 256) acc |= ei32[2 * j + 1];
        if (acc) atomicOr(&sflag, 1);
        __syncthreads();
        if (threadIdx.x == 0) g_is64 = (sflag == 0) ? 1 : 0;
    }
}

// ---------------- convert edges + histogram ----------------
__global__ void k_convert(const void* __restrict__ ei) {
    int e = blockIdx.x * blockDim.x + threadIdx.x;
    if (e >= ETOT) return;
    int s, d;
    if (e >= EE) {                      // self loops
        s = d = e - EE;
    } else if (g_is64) {
        const long long* p = (const long long*)ei;
        s = (int)p[e]; d = (int)p[EE + e];
    } else {
        const int* p = (const int*)ei;
        s = p[e]; d = p[EE + e];
    }
    g_src[e] = s; g_dst[e] = d;
    atomicAdd(&g_deg[d], 1);
}

// ---------------- single-block exclusive scan (50001 row starts) ----------------
__global__ void k_scan() {
    __shared__ int part[1024];
    int t = threadIdx.x;
    const int CH = 49;                   // 1024*49 = 50176 >= NN
    int beg = t * CH, end = min(beg + CH, NN);
    int sum = 0;
    for (int i = beg; i < end; i++) sum += g_deg[i];
    part[t] = sum;
    __syncthreads();
    for (int d = 1; d < 1024; d <<= 1) {
        int v = (t >= d) ? part[t - d] : 0;
        __syncthreads();
        part[t] += v;
        __syncthreads();
    }
    int run = part[t] - sum;             // exclusive prefix
    for (int i = beg; i < end; i++) {
        g_rs[i] = run; g_cur[i] = run; run += g_deg[i];
    }
    if (t == 0) g_rs[NN] = ETOT;
}

// ---------------- scatter into CSR ----------------
__global__ void k_scatter() {
    int e = blockIdx.x * blockDim.x + threadIdx.x;
    if (e >= ETOT) return;
    int d = g_dst[e];
    int p = atomicAdd(&g_cur[d], 1);
    g_csr[p] = g_src[e];
}

// ---------------- GEMM1: [50000,27] @ [27,256], f32x2 packed ----------------
__global__ void __launch_bounds__(256) k_gemm1(const float* __restrict__ x,
                                               const float* __restrict__ W1) {
    __shared__ __align__(16) float sxt[27 * 16];   // transposed [k][m]
    int tid = threadIdx.x;
    int n0 = blockIdx.x * 16;                      // 50000 = 3125*16
    for (int i = tid; i < 27 * 16; i += 256) {
        int k = i >> 4, m = i & 15;
        sxt[i] = x[(n0 + m) * 27 + k];
    }
    float w[27];
#pragma unroll
    for (int k = 0; k < 27; k++) w[k] = W1[k * 256 + tid];
    __syncthreads();
    ull acc[8];
#pragma unroll
    for (int p = 0; p < 8; p++) acc[p] = 0ull;
#pragma unroll
    for (int k = 0; k < 27; k++) {
        ull wp = pack2(w[k], w[k]);
        const ulonglong2* xp = (const ulonglong2*)(sxt + k * 16);
#pragma unroll
        for (int q = 0; q < 4; q++) {
            ulonglong2 xv = xp[q];
            acc[2 * q]     = fma2(xv.x, wp, acc[2 * q]);
            acc[2 * q + 1] = fma2(xv.y, wp, acc[2 * q + 1]);
        }
    }
#pragma unroll
    for (int p = 0; p < 8; p++) {
        float lo, hi; unpack2(acc[p], lo, hi);
        g_h1[(size_t)(n0 + 2 * p) * 256 + tid] = lo;
        g_h1[(size_t)(n0 + 2 * p + 1) * 256 + tid] = hi;
    }
}

// ---------------- per-node half scores ----------------
__global__ void __launch_bounds__(256) k_scores1(const float* __restrict__ a_src,
                                                 const float* __restrict__ a_dst) {
    int widx = threadIdx.x >> 5, lane = threadIdx.x & 31;
    int n = blockIdx.x * 2 + (widx >> 2);          // 2 nodes / block
    int head = widx & 3;
    const float* hp = g_h1 + (size_t)n * 256 + head * 64;
    float v0 = hp[lane], v1 = hp[lane + 32];
    float ps = v0 * a_src[head * 64 + lane] + v1 * a_src[head * 64 + lane + 32];
    float pd = v0 * a_dst[head * 64 + lane] + v1 * a_dst[head * 64 + lane + 32];
#pragma unroll
    for (int o = 16; o; o >>= 1) {
        ps += __shfl_down_sync(0xFFFFFFFFu, ps, o);
        pd += __shfl_down_sync(0xFFFFFFFFu, pd, o);
    }
    if (lane == 0) { g_ssrc1[n * 4 + head] = ps; g_sdst1[n * 4 + head] = pd; }
}

__global__ void __launch_bounds__(256) k_scores2(const float* __restrict__ a_src,
                                                 const float* __restrict__ a_dst) {
    int widx = threadIdx.x >> 5, lane = threadIdx.x & 31;
    int n = blockIdx.x * 4 + (widx >> 1);          // 4 nodes / block
    int head = widx & 1;
    const float* hp = g_h2 + (size_t)n * 128 + head * 64;
    float v0 = hp[lane], v1 = hp[lane + 32];
    float ps = v0 * a_src[head * 64 + lane] + v1 * a_src[head * 64 + lane + 32];
    float pd = v0 * a_dst[head * 64 + lane] + v1 * a_dst[head * 64 + lane + 32];
#pragma unroll
    for (int o = 16; o; o >>= 1) {
        ps += __shfl_down_sync(0xFFFFFFFFu, ps, o);
        pd += __shfl_down_sync(0xFFFFFFFFu, pd, o);
    }
    if (lane == 0) { g_ssrc2[n * 2 + head] = ps; g_sdst2[n * 2 + head] = pd; }
}

// ---------------- layer-1 aggregation: warp / dst, atomic-free ----------------
// fused: segment max + exp + weighted sum + z + normalize + bias + ELU
__global__ void __launch_bounds__(256) k_agg1(const float* __restrict__ b1) {
    int wid = (blockIdx.x * blockDim.x + threadIdx.x) >> 5;
    if (wid >= NN) return;
    int lane = threadIdx.x & 31;
    int rs = g_rs[wid], re = g_rs[wid + 1];
    float4 sd = *(const float4*)(g_sdst1 + wid * 4);

    // pass 1: per-head max
    float4 mx = make_float4(-3.4e38f, -3.4e38f, -3.4e38f, -3.4e38f);
    for (int j = rs + lane; j < re; j += 32) {
        int s = g_csr[j];
        float4 ss = *(const float4*)(g_ssrc1 + s * 4);
        mx.x = fmaxf(mx.x, lrelu(ss.x + sd.x));
        mx.y = fmaxf(mx.y, lrelu(ss.y + sd.y));
        mx.z = fmaxf(mx.z, lrelu(ss.z + sd.z));
        mx.w = fmaxf(mx.w, lrelu(ss.w + sd.w));
    }
#pragma unroll
    for (int o = 16; o; o >>= 1) {
        mx.x = fmaxf(mx.x, __shfl_xor_sync(0xFFFFFFFFu, mx.x, o));
        mx.y = fmaxf(mx.y, __shfl_xor_sync(0xFFFFFFFFu, mx.y, o));
        mx.z = fmaxf(mx.z, __shfl_xor_sync(0xFFFFFFFFu, mx.z, o));
        mx.w = fmaxf(mx.w, __shfl_xor_sync(0xFFFFFFFFu, mx.w, o));
    }

    // pass 2: exp weights + weighted gather-accumulate
    float4 zv = make_float4(0.f, 0.f, 0.f, 0.f);
    float4 accLo = make_float4(0.f, 0.f, 0.f, 0.f);
    float4 accHi = make_float4(0.f, 0.f, 0.f, 0.f);
    for (int base = rs; base < re; base += 32) {
        int cnt = min(32, re - base);
        int s_l = 0;
        float4 wv = make_float4(0.f, 0.f, 0.f, 0.f);
        if (lane < cnt) {
            s_l = g_csr[base + lane];
            float4 ss = *(const float4*)(g_ssrc1 + s_l * 4);
            wv.x = __expf(lrelu(ss.x + sd.x) - mx.x);
            wv.y = __expf(lrelu(ss.y + sd.y) - mx.y);
            wv.z = __expf(lrelu(ss.z + sd.z) - mx.z);
            wv.w = __expf(lrelu(ss.w + sd.w) - mx.w);
            zv.x += wv.x; zv.y += wv.y; zv.z += wv.z; zv.w += wv.w;
        }
        for (int t = 0; t < cnt; t++) {
            int s    = __shfl_sync(0xFFFFFFFFu, s_l, t);
            float w0 = __shfl_sync(0xFFFFFFFFu, wv.x, t);
            float w1 = __shfl_sync(0xFFFFFFFFu, wv.y, t);
            float w2 = __shfl_sync(0xFFFFFFFFu, wv.z, t);
            float w3 = __shfl_sync(0xFFFFFFFFu, wv.w, t);
            const float4* hp = (const float4*)(g_h1 + (size_t)s * 256);
            float4 hLo = hp[lane];          // cols lane*4 .. +3     (heads 0/1)
            float4 hHi = hp[32 + lane];     // cols 128+lane*4 ..    (heads 2/3)
            float wa = (lane < 16) ? w0 : w1;
            float wb = (lane < 16) ? w2 : w3;
            accLo.x = fmaf(wa, hLo.x, accLo.x);
            accLo.y = fmaf(wa, hLo.y, accLo.y);
            accLo.z = fmaf(wa, hLo.z, accLo.z);
            accLo.w = fmaf(wa, hLo.w, accLo.w);
            accHi.x = fmaf(wb, hHi.x, accHi.x);
            accHi.y = fmaf(wb, hHi.y, accHi.y);
            accHi.z = fmaf(wb, hHi.z, accHi.z);
            accHi.w = fmaf(wb, hHi.w, accHi.w);
        }
    }
#pragma unroll
    for (int o = 16; o; o >>= 1) {
        zv.x += __shfl_xor_sync(0xFFFFFFFFu, zv.x, o);
        zv.y += __shfl_xor_sync(0xFFFFFFFFu, zv.y, o);
        zv.z += __shfl_xor_sync(0xFFFFFFFFu, zv.z, o);
        zv.w += __shfl_xor_sync(0xFFFFFFFFu, zv.w, o);
    }
    float za = ((lane < 16) ? zv.x : zv.y) + EPS;
    float zb = ((lane < 16) ? zv.z : zv.w) + EPS;
    float4 bLo = *(const float4*)(b1 + lane * 4);
    float4 bHi = *(const float4*)(b1 + 128 + lane * 4);
    float4 v;
    v.x = elu(accLo.x / za + bLo.x);
    v.y = elu(accLo.y / za + bLo.y);
    v.z = elu(accLo.z / za + bLo.z);
    v.w = elu(accLo.w / za + bLo.w);
    *(float4*)(g_out1 + (size_t)wid * 256 + lane * 4) = v;
    v.x = elu(accHi.x / zb + bHi.x);
    v.y = elu(accHi.y / zb + bHi.y);
    v.z = elu(accHi.z / zb + bHi.z);
    v.w = elu(accHi.w / zb + bHi.w);
    *(float4*)(g_out1 + (size_t)wid * 256 + 128 + lane * 4) = v;
}

// ---------------- GEMM2: [50000,256] @ [256,128], f32x2 packed ----------------
__global__ void __launch_bounds__(256) k_gemm2(const float* __restrict__ W2) {
    __shared__ __align__(16) float sxt[256 * 36];  // [k][m], stride 36 (pad)
    int tid = threadIdx.x;
    int n0 = blockIdx.x * 32;
    int cnt = min(32, NN - n0);
    if (cnt < 32) {
        for (int i = tid; i < 256 * 36; i += 256) sxt[i] = 0.f;
        __syncthreads();
    }
    for (int i = tid; i < cnt * 256; i += 256) {
        int m = i >> 8, k = i & 255;
        sxt[k * 36 + m] = g_out1[(size_t)(n0 + m) * 256 + k];
    }
    __syncthreads();
    int col = tid & 127;
    int g = tid >> 7;                              // node group: g*16 .. g*16+15
    ull acc[8];
#pragma unroll
    for (int p = 0; p < 8; p++) acc[p] = 0ull;
#pragma unroll 4
    for (int k = 0; k < 256; k++) {
        float wv = W2[k * 128 + col];
        ull wp = pack2(wv, wv);
        const ulonglong2* xp = (const ulonglong2*)(sxt + k * 36 + g * 16);
#pragma unroll
        for (int q = 0; q < 4; q++) {
            ulonglong2 xv = xp[q];
            acc[2 * q]     = fma2(xv.x, wp, acc[2 * q]);
            acc[2 * q + 1] = fma2(xv.y, wp, acc[2 * q + 1]);
        }
    }
#pragma unroll
    for (int p = 0; p < 8; p++) {
        float lo, hi; unpack2(acc[p], lo, hi);
        int m = g * 16 + 2 * p;
        if (m < cnt)     g_h2[(size_t)(n0 + m) * 128 + col] = lo;
        if (m + 1 < cnt) g_h2[(size_t)(n0 + m + 1) * 128 + col] = hi;
    }
}

// ---------------- layer-2 aggregation + FC + sigmoid, warp / dst ----------------
__global__ void __launch_bounds__(256) k_agg2(const float* __restrict__ b2,
                                              const float* __restrict__ Wfc,
                                              const float* __restrict__ bfc,
                                              float* __restrict__ out) {
    int wid = (blockIdx.x * blockDim.x + threadIdx.x) >> 5;
    if (wid >= NN) return;
    int lane = threadIdx.x & 31;
    int rs = g_rs[wid], re = g_rs[wid + 1];
    float2 sd = *(const float2*)(g_sdst2 + wid * 2);

    float2 mx = make_float2(-3.4e38f, -3.4e38f);
    for (int j = rs + lane; j < re; j += 32) {
        int s = g_csr[j];
        float2 ss = *(const float2*)(g_ssrc2 + s * 2);
        mx.x = fmaxf(mx.x, lrelu(ss.x + sd.x));
        mx.y = fmaxf(mx.y, lrelu(ss.y + sd.y));
    }
#pragma unroll
    for (int o = 16; o; o >>= 1) {
        mx.x = fmaxf(mx.x, __shfl_xor_sync(0xFFFFFFFFu, mx.x, o));
        mx.y = fmaxf(mx.y, __shfl_xor_sync(0xFFFFFFFFu, mx.y, o));
    }

    float2 zv = make_float2(0.f, 0.f);
    float4 acc = make_float4(0.f, 0.f, 0.f, 0.f);
    for (int base = rs; base < re; base += 32) {
        int cnt = min(32, re - base);
        int s_l = 0;
        float2 wv = make_float2(0.f, 0.f);
        if (lane < cnt) {
            s_l = g_csr[base + lane];
            float2 ss = *(const float2*)(g_ssrc2 + s_l * 2);
            wv.x = __expf(lrelu(ss.x + sd.x) - mx.x);
            wv.y = __expf(lrelu(ss.y + sd.y) - mx.y);
            zv.x += wv.x; zv.y += wv.y;
        }
        for (int t = 0; t < cnt; t++) {
            int s    = __shfl_sync(0xFFFFFFFFu, s_l, t);
            float w0 = __shfl_sync(0xFFFFFFFFu, wv.x, t);
            float w1 = __shfl_sync(0xFFFFFFFFu, wv.y, t);
            const float4* hp = (const float4*)(g_h2 + (size_t)s * 128);
            float4 h = hp[lane];            // cols lane*4 .. +3
            float wa = (lane < 16) ? w0 : w1;
            acc.x = fmaf(wa, h.x, acc.x);
            acc.y = fmaf(wa, h.y, acc.y);
            acc.z = fmaf(wa, h.z, acc.z);
            acc.w = fmaf(wa, h.w, acc.w);
        }
    }
#pragma unroll
    for (int o = 16; o; o >>= 1) {
        zv.x += __shfl_xor_sync(0xFFFFFFFFu, zv.x, o);
        zv.y += __shfl_xor_sync(0xFFFFFFFFu, zv.y, o);
    }
    float za = ((lane < 16) ? zv.x : zv.y) + EPS;
    float4 b = *(const float4*)(b2 + lane * 4);
    float4 wf = *(const float4*)(Wfc + lane * 4);
    float t = elu(acc.x / za + b.x) * wf.x
            + elu(acc.y / za + b.y) * wf.y
            + elu(acc.z / za + b.z) * wf.z
            + elu(acc.w / za + b.w) * wf.w;
#pragma unroll
    for (int o = 16; o; o >>= 1) t += __shfl_down_sync(0xFFFFFFFFu, t, o);
    if (lane == 0) {
        float s = t + bfc[0];
        out[wid] = 1.f / (1.f + __expf(-s));
    }
}

// ---------------- launch ----------------
extern "C" void kernel_launch(void* const* d_in, const int* in_sizes, int n_in,
                              void* d_out, int out_size) {
    const float* x      = (const float*)d_in[0];
    const void*  ei     = d_in[1];
    const float* W1     = (const float*)d_in[2];
    const float* a_src1 = (const float*)d_in[3];
    const float* a_dst1 = (const float*)d_in[4];
    const float* b1     = (const float*)d_in[5];
    const float* W2     = (const float*)d_in[6];
    const float* a_src2 = (const float*)d_in[7];
    const float* a_dst2 = (const float*)d_in[8];
    const float* b2     = (const float*)d_in[9];
    const float* Wfc    = (const float*)d_in[10];
    const float* bfc    = (const float*)d_in[11];
    float* out = (float*)d_out;

    // CSR build
    k_prep<<<64, 256>>>((const int*)ei);
    k_convert<<<(ETOT + 255) / 256, 256>>>(ei);
    k_scan<<<1, 1024>>>();
    k_scatter<<<(ETOT + 255) / 256, 256>>>();

    // layer 1
    k_gemm1<<<NN / 16, 256>>>(x, W1);
    k_scores1<<<NN / 2, 256>>>(a_src1, a_dst1);
    k_agg1<<<(NN + 7) / 8, 256>>>(b1);

    // layer 2
    k_gemm2<<<(NN + 31) / 32, 256>>>(W2);
    k_scores2<<<NN / 4, 256>>>(a_src2, a_dst2);
    k_agg2<<<(NN + 7) / 8, 256>>>(b2, Wfc, bfc, out);
}

// round 4
// speedup vs baseline: 2.1263x; 1.2584x over previous
#include <cuda_runtime.h>
#include <cuda_bf16.h>

#define NN 50000
#define EE 300000
#define ETOT (EE + NN)          // edges + self loops
#define NEG_SLOPE 0.2f
#define EPS 1e-16f
#define SCAN_B 512
#define NBLK ((NN + SCAN_B - 1) / SCAN_B)   // 98

typedef unsigned long long ull;

// ---------------- scratch (static device allocations only) ----------------
__device__ int g_srcR[ETOT];
__device__ int g_dstR[ETOT];
__device__ int g_rank[ETOT];     // within-dst-segment rank (from atomic order)
__device__ int g_csr[ETOT];      // src ids sorted by dst
__device__ int g_deg[NN];
__device__ int g_rs[NN + 1];     // row starts
__device__ int g_bsum[NBLK];
__device__ int g_boff[NBLK];
__device__ int g_is64;

__device__ float g_h1[NN * 256];
__device__ float g_ssrc1[NN * 4];
__device__ float g_sdst1[NN * 4];
__device__ float g_out1[NN * 256];   // layer-1 ELU output

__device__ float g_h2[NN * 128];
__device__ float g_ssrc2[NN * 2];
__device__ float g_sdst2[NN * 2];

// ---------------- helpers ----------------
__device__ __forceinline__ float lrelu(float x) {
    return x > 0.f ? x : NEG_SLOPE * x;
}
__device__ __forceinline__ float elu(float x) {
    return x > 0.f ? x : expm1f(x);
}
__device__ __forceinline__ ull pack2(float a, float b) {
    ull r; asm("mov.b64 %0,{%1,%2};" : "=l"(r) : "f"(a), "f"(b)); return r;
}
__device__ __forceinline__ void unpack2(ull p, float& a, float& b) {
    asm("mov.b64 {%0,%1},%2;" : "=f"(a), "=f"(b) : "l"(p));
}
__device__ __forceinline__ ull fma2(ull a, ull b, ull c) {
    ull d; asm("fma.rn.f32x2 %0,%1,%2,%3;" : "=l"(d) : "l"(a), "l"(b), "l"(c));
    return d;
}

// ---------------- prep: zero deg + dtype detect ----------------
__global__ void k_prep(const int* __restrict__ ei32) {
    int i = blockIdx.x * blockDim.x + threadIdx.x;
    for (int j = i; j < NN; j += gridDim.x * blockDim.x) g_deg[j] = 0;
    if (blockIdx.x == 0) {
        __shared__ int sflag;
        if (threadIdx.x == 0) sflag = 0;
        __syncthreads();
        int acc = 0;
        for (int j = threadIdx.x; j < 2048; j += 256) acc |= ei32[2 * j + 1];
        if (acc) atomicOr(&sflag, 1);
        __syncthreads();
        if (threadIdx.x == 0) g_is64 = (sflag == 0) ? 1 : 0;
    }
}

// ---------------- convert edges + histogram + rank ----------------
__global__ void k_convert(const void* __restrict__ ei) {
    int e = blockIdx.x * blockDim.x + threadIdx.x;
    if (e >= ETOT) return;
    int s, d;
    if (e >= EE) {                      // self loops
        s = d = e - EE;
    } else if (g_is64) {
        const long long* p = (const long long*)ei;
        s = (int)p[e]; d = (int)p[EE + e];
    } else {
        const int* p = (const int*)ei;
        s = p[e]; d = p[EE + e];
    }
    g_srcR[e] = s; g_dstR[e] = d;
    g_rank[e] = atomicAdd(&g_deg[d], 1);
}

// ---------------- 3-phase multi-block exclusive scan ----------------
__global__ void __launch_bounds__(SCAN_B) k_scanA() {
    __shared__ int sh[SCAN_B];
    int b = blockIdx.x, t = threadIdx.x;
    int i = b * SCAN_B + t;
    int v = (i < NN) ? g_deg[i] : 0;
    sh[t] = v;
    __syncthreads();
#pragma unroll
    for (int d = 1; d < SCAN_B; d <<= 1) {
        int u = (t >= d) ? sh[t - d] : 0;
        __syncthreads();
        sh[t] += u;
        __syncthreads();
    }
    if (i < NN) g_rs[i] = sh[t] - v;          // block-local exclusive
    if (t == SCAN_B - 1) g_bsum[b] = sh[t];
}

__global__ void k_scanB() {
    __shared__ int sh[128];
    int t = threadIdx.x;
    int v = (t < NBLK) ? g_bsum[t] : 0;
    sh[t] = v;
    __syncthreads();
#pragma unroll
    for (int d = 1; d < 128; d <<= 1) {
        int u = (t >= d) ? sh[t - d] : 0;
        __syncthreads();
        sh[t] += u;
        __syncthreads();
    }
    if (t < NBLK) g_boff[t] = sh[t] - v;      // exclusive
}

__global__ void __launch_bounds__(SCAN_B) k_scanC() {
    int i = blockIdx.x * SCAN_B + threadIdx.x;
    if (i < NN) g_rs[i] += g_boff[blockIdx.x];
    if (i == 0) g_rs[NN] = ETOT;
}

// ---------------- scatter into CSR (no atomics) ----------------
__global__ void k_scatter() {
    int e = blockIdx.x * blockDim.x + threadIdx.x;
    if (e >= ETOT) return;
    int d = g_dstR[e];
    g_csr[g_rs[d] + g_rank[e]] = g_srcR[e];
}

// ---------------- GEMM1: [50000,27] @ [27,256], f32x2 packed ----------------
__global__ void __launch_bounds__(256) k_gemm1(const float* __restrict__ x,
                                               const float* __restrict__ W1) {
    __shared__ __align__(16) float sxt[27 * 16];   // transposed [k][m]
    int tid = threadIdx.x;
    int n0 = blockIdx.x * 16;                      // 50000 = 3125*16
    for (int i = tid; i < 27 * 16; i += 256) {
        int k = i >> 4, m = i & 15;
        sxt[i] = x[(n0 + m) * 27 + k];
    }
    float w[27];
#pragma unroll
    for (int k = 0; k < 27; k++) w[k] = W1[k * 256 + tid];
    __syncthreads();
    ull acc[8];
#pragma unroll
    for (int p = 0; p < 8; p++) acc[p] = 0ull;
#pragma unroll
    for (int k = 0; k < 27; k++) {
        ull wp = pack2(w[k], w[k]);
        const ulonglong2* xp = (const ulonglong2*)(sxt + k * 16);
#pragma unroll
        for (int q = 0; q < 4; q++) {
            ulonglong2 xv = xp[q];
            acc[2 * q]     = fma2(xv.x, wp, acc[2 * q]);
            acc[2 * q + 1] = fma2(xv.y, wp, acc[2 * q + 1]);
        }
    }
#pragma unroll
    for (int p = 0; p < 8; p++) {
        float lo, hi; unpack2(acc[p], lo, hi);
        g_h1[(size_t)(n0 + 2 * p) * 256 + tid] = lo;
        g_h1[(size_t)(n0 + 2 * p + 1) * 256 + tid] = hi;
    }
}

// ---------------- per-node half scores ----------------
__global__ void __launch_bounds__(256) k_scores1(const float* __restrict__ a_src,
                                                 const float* __restrict__ a_dst) {
    int widx = threadIdx.x >> 5, lane = threadIdx.x & 31;
    int n = blockIdx.x * 2 + (widx >> 2);          // 2 nodes / block
    int head = widx & 3;
    const float* hp = g_h1 + (size_t)n * 256 + head * 64;
    float v0 = hp[lane], v1 = hp[lane + 32];
    float ps = v0 * a_src[head * 64 + lane] + v1 * a_src[head * 64 + lane + 32];
    float pd = v0 * a_dst[head * 64 + lane] + v1 * a_dst[head * 64 + lane + 32];
#pragma unroll
    for (int o = 16; o; o >>= 1) {
        ps += __shfl_down_sync(0xFFFFFFFFu, ps, o);
        pd += __shfl_down_sync(0xFFFFFFFFu, pd, o);
    }
    if (lane == 0) { g_ssrc1[n * 4 + head] = ps; g_sdst1[n * 4 + head] = pd; }
}

__global__ void __launch_bounds__(256) k_scores2(const float* __restrict__ a_src,
                                                 const float* __restrict__ a_dst) {
    int widx = threadIdx.x >> 5, lane = threadIdx.x & 31;
    int n = blockIdx.x * 4 + (widx >> 1);          // 4 nodes / block
    int head = widx & 1;
    const float* hp = g_h2 + (size_t)n * 128 + head * 64;
    float v0 = hp[lane], v1 = hp[lane + 32];
    float ps = v0 * a_src[head * 64 + lane] + v1 * a_src[head * 64 + lane + 32];
    float pd = v0 * a_dst[head * 64 + lane] + v1 * a_dst[head * 64 + lane + 32];
#pragma unroll
    for (int o = 16; o; o >>= 1) {
        ps += __shfl_down_sync(0xFFFFFFFFu, ps, o);
        pd += __shfl_down_sync(0xFFFFFFFFu, pd, o);
    }
    if (lane == 0) { g_ssrc2[n * 2 + head] = ps; g_sdst2[n * 2 + head] = pd; }
}

// ---------------- layer-1 aggregation: warp / dst, atomic-free ----------------
__global__ void __launch_bounds__(256) k_agg1(const float* __restrict__ b1) {
    __shared__ __align__(16) float4 s_w4[8][32];
    __shared__ int s_si[8][32];
    int wid = (blockIdx.x * blockDim.x + threadIdx.x) >> 5;
    if (wid >= NN) return;
    int wip = threadIdx.x >> 5;
    int lane = threadIdx.x & 31;
    int rs = g_rs[wid], re = g_rs[wid + 1];
    float4 sd = *(const float4*)(g_sdst1 + wid * 4);

    // pass 1: per-head max
    float4 mx = make_float4(-3.4e38f, -3.4e38f, -3.4e38f, -3.4e38f);
    for (int j = rs + lane; j < re; j += 32) {
        int s = g_csr[j];
        float4 ss = *(const float4*)(g_ssrc1 + s * 4);
        mx.x = fmaxf(mx.x, lrelu(ss.x + sd.x));
        mx.y = fmaxf(mx.y, lrelu(ss.y + sd.y));
        mx.z = fmaxf(mx.z, lrelu(ss.z + sd.z));
        mx.w = fmaxf(mx.w, lrelu(ss.w + sd.w));
    }
#pragma unroll
    for (int o = 16; o; o >>= 1) {
        mx.x = fmaxf(mx.x, __shfl_xor_sync(0xFFFFFFFFu, mx.x, o));
        mx.y = fmaxf(mx.y, __shfl_xor_sync(0xFFFFFFFFu, mx.y, o));
        mx.z = fmaxf(mx.z, __shfl_xor_sync(0xFFFFFFFFu, mx.z, o));
        mx.w = fmaxf(mx.w, __shfl_xor_sync(0xFFFFFFFFu, mx.w, o));
    }

    // pass 2: exp weights (staged in smem) + weighted gather-accumulate
    float4 zv = make_float4(0.f, 0.f, 0.f, 0.f);
    float4 accLo = make_float4(0.f, 0.f, 0.f, 0.f);
    float4 accHi = make_float4(0.f, 0.f, 0.f, 0.f);
    for (int base = rs; base < re; base += 32) {
        int cnt = min(32, re - base);
        int s_l = 0;
        float4 wv = make_float4(0.f, 0.f, 0.f, 0.f);
        if (lane < cnt) {
            s_l = g_csr[base + lane];
            float4 ss = *(const float4*)(g_ssrc1 + s_l * 4);
            wv.x = __expf(lrelu(ss.x + sd.x) - mx.x);
            wv.y = __expf(lrelu(ss.y + sd.y) - mx.y);
            wv.z = __expf(lrelu(ss.z + sd.z) - mx.z);
            wv.w = __expf(lrelu(ss.w + sd.w) - mx.w);
            zv.x += wv.x; zv.y += wv.y; zv.z += wv.z; zv.w += wv.w;
        }
        __syncwarp();
        s_w4[wip][lane] = wv;
        s_si[wip][lane] = s_l;
        __syncwarp();
        for (int t = 0; t < cnt; t++) {
            float4 w4 = s_w4[wip][t];
            int s = s_si[wip][t];
            const float4* hp = (const float4*)(g_h1 + (size_t)s * 256);
            float4 hLo = hp[lane];          // cols lane*4 .. +3     (heads 0/1)
            float4 hHi = hp[32 + lane];     // cols 128+lane*4 ..    (heads 2/3)
            float wa = (lane < 16) ? w4.x : w4.y;
            float wb = (lane < 16) ? w4.z : w4.w;
            accLo.x = fmaf(wa, hLo.x, accLo.x);
            accLo.y = fmaf(wa, hLo.y, accLo.y);
            accLo.z = fmaf(wa, hLo.z, accLo.z);
            accLo.w = fmaf(wa, hLo.w, accLo.w);
            accHi.x = fmaf(wb, hHi.x, accHi.x);
            accHi.y = fmaf(wb, hHi.y, accHi.y);
            accHi.z = fmaf(wb, hHi.z, accHi.z);
            accHi.w = fmaf(wb, hHi.w, accHi.w);
        }
    }
#pragma unroll
    for (int o = 16; o; o >>= 1) {
        zv.x += __shfl_xor_sync(0xFFFFFFFFu, zv.x, o);
        zv.y += __shfl_xor_sync(0xFFFFFFFFu, zv.y, o);
        zv.z += __shfl_xor_sync(0xFFFFFFFFu, zv.z, o);
        zv.w += __shfl_xor_sync(0xFFFFFFFFu, zv.w, o);
    }
    float ia = __fdividef(1.f, ((lane < 16) ? zv.x : zv.y) + EPS);
    float ib = __fdividef(1.f, ((lane < 16) ? zv.z : zv.w) + EPS);
    float4 bLo = *(const float4*)(b1 + lane * 4);
    float4 bHi = *(const float4*)(b1 + 128 + lane * 4);
    float4 v;
    v.x = elu(fmaf(accLo.x, ia, bLo.x));
    v.y = elu(fmaf(accLo.y, ia, bLo.y));
    v.z = elu(fmaf(accLo.z, ia, bLo.z));
    v.w = elu(fmaf(accLo.w, ia, bLo.w));
    *(float4*)(g_out1 + (size_t)wid * 256 + lane * 4) = v;
    v.x = elu(fmaf(accHi.x, ib, bHi.x));
    v.y = elu(fmaf(accHi.y, ib, bHi.y));
    v.z = elu(fmaf(accHi.z, ib, bHi.z));
    v.w = elu(fmaf(accHi.w, ib, bHi.w));
    *(float4*)(g_out1 + (size_t)wid * 256 + 128 + lane * 4) = v;
}

// ---------------- GEMM2: [50000,256] @ [256,128], f32x2 packed ----------------
__global__ void __launch_bounds__(256) k_gemm2(const float* __restrict__ W2) {
    __shared__ __align__(16) float sxt[256 * 36];  // [k][m], stride 36 (pad)
    int tid = threadIdx.x;
    int n0 = blockIdx.x * 32;
    int cnt = min(32, NN - n0);
    if (cnt < 32) {
        for (int i = tid; i < 256 * 36; i += 256) sxt[i] = 0.f;
        __syncthreads();
    }
    for (int i = tid; i < cnt * 256; i += 256) {
        int m = i >> 8, k = i & 255;
        sxt[k * 36 + m] = g_out1[(size_t)(n0 + m) * 256 + k];
    }
    __syncthreads();
    int col = tid & 127;
    int g = tid >> 7;                              // node group: g*16 .. g*16+15
    ull acc[8];
#pragma unroll
    for (int p = 0; p < 8; p++) acc[p] = 0ull;
#pragma unroll 4
    for (int k = 0; k < 256; k++) {
        float wv = W2[k * 128 + col];
        ull wp = pack2(wv, wv);
        const ulonglong2* xp = (const ulonglong2*)(sxt + k * 36 + g * 16);
#pragma unroll
        for (int q = 0; q < 4; q++) {
            ulonglong2 xv = xp[q];
            acc[2 * q]     = fma2(xv.x, wp, acc[2 * q]);
            acc[2 * q + 1] = fma2(xv.y, wp, acc[2 * q + 1]);
        }
    }
#pragma unroll
    for (int p = 0; p < 8; p++) {
        float lo, hi; unpack2(acc[p], lo, hi);
        int m = g * 16 + 2 * p;
        if (m < cnt)     g_h2[(size_t)(n0 + m) * 128 + col] = lo;
        if (m + 1 < cnt) g_h2[(size_t)(n0 + m + 1) * 128 + col] = hi;
    }
}

// ---------------- layer-2 aggregation + FC + sigmoid, warp / dst ----------------
__global__ void __launch_bounds__(256) k_agg2(const float* __restrict__ b2,
                                              const float* __restrict__ Wfc,
                                              const float* __restrict__ bfc,
                                              float* __restrict__ out) {
    __shared__ __align__(8) float2 s_w2[8][32];
    __shared__ int s_si[8][32];
    int wid = (blockIdx.x * blockDim.x + threadIdx.x) >> 5;
    if (wid >= NN) return;
    int wip = threadIdx.x >> 5;
    int lane = threadIdx.x & 31;
    int rs = g_rs[wid], re = g_rs[wid + 1];
    float2 sd = *(const float2*)(g_sdst2 + wid * 2);

    float2 mx = make_float2(-3.4e38f, -3.4e38f);
    for (int j = rs + lane; j < re; j += 32) {
        int s = g_csr[j];
        float2 ss = *(const float2*)(g_ssrc2 + s * 2);
        mx.x = fmaxf(mx.x, lrelu(ss.x + sd.x));
        mx.y = fmaxf(mx.y, lrelu(ss.y + sd.y));
    }
#pragma unroll
    for (int o = 16; o; o >>= 1) {
        mx.x = fmaxf(mx.x, __shfl_xor_sync(0xFFFFFFFFu, mx.x, o));
        mx.y = fmaxf(mx.y, __shfl_xor_sync(0xFFFFFFFFu, mx.y, o));
    }

    float2 zv = make_float2(0.f, 0.f);
    float4 acc = make_float4(0.f, 0.f, 0.f, 0.f);
    for (int base = rs; base < re; base += 32) {
        int cnt = min(32, re - base);
        int s_l = 0;
        float2 wv = make_float2(0.f, 0.f);
        if (lane < cnt) {
            s_l = g_csr[base + lane];
            float2 ss = *(const float2*)(g_ssrc2 + s_l * 2);
            wv.x = __expf(lrelu(ss.x + sd.x) - mx.x);
            wv.y = __expf(lrelu(ss.y + sd.y) - mx.y);
            zv.x += wv.x; zv.y += wv.y;
        }
        __syncwarp();
        s_w2[wip][lane] = wv;
        s_si[wip][lane] = s_l;
        __syncwarp();
        for (int t = 0; t < cnt; t++) {
            float2 w2 = s_w2[wip][t];
            int s = s_si[wip][t];
            const float4* hp = (const float4*)(g_h2 + (size_t)s * 128);
            float4 h = hp[lane];            // cols lane*4 .. +3
            float wa = (lane < 16) ? w2.x : w2.y;
            acc.x = fmaf(wa, h.x, acc.x);
            acc.y = fmaf(wa, h.y, acc.y);
            acc.z = fmaf(wa, h.z, acc.z);
            acc.w = fmaf(wa, h.w, acc.w);
        }
    }
#pragma unroll
    for (int o = 16; o; o >>= 1) {
        zv.x += __shfl_xor_sync(0xFFFFFFFFu, zv.x, o);
        zv.y += __shfl_xor_sync(0xFFFFFFFFu, zv.y, o);
    }
    float iz = __fdividef(1.f, ((lane < 16) ? zv.x : zv.y) + EPS);
    float4 b = *(const float4*)(b2 + lane * 4);
    float4 wf = *(const float4*)(Wfc + lane * 4);
    float t = elu(fmaf(acc.x, iz, b.x)) * wf.x
            + elu(fmaf(acc.y, iz, b.y)) * wf.y
            + elu(fmaf(acc.z, iz, b.z)) * wf.z
            + elu(fmaf(acc.w, iz, b.w)) * wf.w;
#pragma unroll
    for (int o = 16; o; o >>= 1) t += __shfl_down_sync(0xFFFFFFFFu, t, o);
    if (lane == 0) {
        float s = t + bfc[0];
        out[wid] = __fdividef(1.f, 1.f + __expf(-s));
    }
}

// ---------------- launch ----------------
extern "C" void kernel_launch(void* const* d_in, const int* in_sizes, int n_in,
                              void* d_out, int out_size) {
    const float* x      = (const float*)d_in[0];
    const void*  ei     = d_in[1];
    const float* W1     = (const float*)d_in[2];
    const float* a_src1 = (const float*)d_in[3];
    const float* a_dst1 = (const float*)d_in[4];
    const float* b1     = (const float*)d_in[5];
    const float* W2     = (const float*)d_in[6];
    const float* a_src2 = (const float*)d_in[7];
    const float* a_dst2 = (const float*)d_in[8];
    const float* b2     = (const float*)d_in[9];
    const float* Wfc    = (const float*)d_in[10];
    const float* bfc    = (const float*)d_in[11];
    float* out = (float*)d_out;

    // CSR build
    k_prep<<<64, 256>>>((const int*)ei);
    k_convert<<<(ETOT + 255) / 256, 256>>>(ei);
    k_scanA<<<NBLK, SCAN_B>>>();
    k_scanB<<<1, 128>>>();
    k_scanC<<<NBLK, SCAN_B>>>();
    k_scatter<<<(ETOT + 255) / 256, 256>>>();

    // layer 1
    k_gemm1<<<NN / 16, 256>>>(x, W1);
    k_scores1<<<NN / 2, 256>>>(a_src1, a_dst1);
    k_agg1<<<(NN + 7) / 8, 256>>>(b1);

    // layer 2
    k_gemm2<<<(NN + 31) / 32, 256>>>(W2);
    k_scores2<<<NN / 4, 256>>>(a_src2, a_dst2);
    k_agg2<<<(NN + 7) / 8, 256>>>(b2, Wfc, bfc, out);
}

// round 6
// speedup vs baseline: 2.3133x; 1.0879x over previous
#include <cuda_runtime.h>
#include <cuda_bf16.h>

#define NN 50000
#define EE 300000
#define ETOT (EE + NN)          // edges + self loops
#define NEG_SLOPE 0.2f
#define EPS 1e-16f
#define SCAN_B 512
#define NBLK ((NN + SCAN_B - 1) / SCAN_B)   // 98

typedef unsigned long long ull;

// ---------------- scratch (static device allocations only) ----------------
// INVARIANT: g_deg and g_pub are zero at every kernel_launch entry.
// (zero-initialized at load; re-zeroed at the start of k_agg2 each call)
__device__ int g_srcR[ETOT];
__device__ int g_dstR[ETOT];
__device__ int g_rank[ETOT];     // within-dst-segment rank (from atomic order)
__device__ int g_csr[ETOT];      // src ids sorted by dst
__device__ int g_deg[NN];
__device__ int g_rs[NN + 1];     // row starts
__device__ int g_pub[NBLK];      // lookback: (block aggregate + 1), 0 = unpublished

__device__ float g_h1[NN * 256];
__device__ float g_ssrc1[NN * 4];
__device__ float g_sdst1[NN * 4];
__device__ float g_out1[NN * 256];   // layer-1 ELU output

__device__ float g_h2[NN * 128];
__device__ float g_ssrc2[NN * 2];
__device__ float g_sdst2[NN * 2];

// ---------------- helpers ----------------
__device__ __forceinline__ float lrelu(float x) {
    return x > 0.f ? x : NEG_SLOPE * x;
}
__device__ __forceinline__ float elu(float x) {
    return x > 0.f ? x : expm1f(x);
}
__device__ __forceinline__ ull pack2(float a, float b) {
    ull r; asm("mov.b64 %0,{%1,%2};" : "=l"(r) : "f"(a), "f"(b)); return r;
}
__device__ __forceinline__ void unpack2(ull p, float& a, float& b) {
    asm("mov.b64 {%0,%1},%2;" : "=f"(a), "=f"(b) : "l"(p));
}
__device__ __forceinline__ ull fma2(ull a, ull b, ull c) {
    ull d; asm("fma.rn.f32x2 %0,%1,%2,%3;" : "=l"(d) : "l"(a), "l"(b), "l"(c));
    return d;
}

// ---------------- convert edges + inline dtype detect + histogram + rank ----
__global__ void __launch_bounds__(256) k_convert(const void* __restrict__ ei) {
    // per-block dtype detect: read odd 32-bit words 1,3,...,511 (same for all
    // blocks). int64 data (values < 50000) -> all high words zero.
    const int* ei32 = (const int*)ei;
    int probe = ei32[2 * threadIdx.x + 1];
    int any = __syncthreads_or(probe);
    int is64 = (any == 0);

    int e = blockIdx.x * blockDim.x + threadIdx.x;
    if (e >= ETOT) return;
    int s, d;
    if (e >= EE) {                      // self loops
        s = d = e - EE;
    } else if (is64) {
        const long long* p = (const long long*)ei;
        s = (int)p[e]; d = (int)p[EE + e];
    } else {
        const int* p = (const int*)ei;
        s = p[e]; d = p[EE + e];
    }
    g_srcR[e] = s; g_dstR[e] = d;
    g_rank[e] = atomicAdd(&g_deg[d], 1);
}

// ---------------- single-pass exclusive scan (aggregate lookback) ----------
// 98 blocks, all resident simultaneously on 148 SMs -> safe to spin.
__global__ void __launch_bounds__(SCAN_B) k_scan() {
    __shared__ int sh[SCAN_B];
    __shared__ int s_sum;
    int b = blockIdx.x, t = threadIdx.x;
    int i = b * SCAN_B + t;
    int v = (i < NN) ? g_deg[i] : 0;
    sh[t] = v;
    __syncthreads();
#pragma unroll
    for (int d = 1; d < SCAN_B; d <<= 1) {
        int u = (t >= d) ? sh[t - d] : 0;
        __syncthreads();
        sh[t] += u;
        __syncthreads();
    }
    int excl = sh[t] - v;                 // block-local exclusive
    int agg = sh[SCAN_B - 1];             // block aggregate
    if (t == 0) {
        s_sum = 0;
        atomicExch(&g_pub[b], agg + 1);   // publish (write-through)
    }
    __syncthreads();
    if (t < b) {                          // sum predecessors' aggregates
        int p;
        do { p = *(volatile int*)&g_pub[t]; } while (p == 0);
        atomicAdd(&s_sum, p - 1);
    }
    __syncthreads();
    if (i < NN) g_rs[i] = excl + s_sum;
    if (b == NBLK - 1 && t == SCAN_B - 1) g_rs[NN] = ETOT;
}

// ---------------- scatter into CSR (no atomics) ----------------
__global__ void k_scatter() {
    int e = blockIdx.x * blockDim.x + threadIdx.x;
    if (e >= ETOT) return;
    int d = g_dstR[e];
    g_csr[g_rs[d] + g_rank[e]] = g_srcR[e];
}

// ---------------- GEMM1 + scores1 fused ----------------
// [50000,27] @ [27,256] f32x2 packed, then per-node per-head half-scores
__global__ void __launch_bounds__(256) k_gemm1s(const float* __restrict__ x,
                                                const float* __restrict__ W1,
                                                const float* __restrict__ a_src1,
                                                const float* __restrict__ a_dst1) {
    __shared__ __align__(16) float sxt[27 * 16];   // transposed [k][m]
    __shared__ __align__(16) float sh1[16 * 256];  // h tile for scores
    int tid = threadIdx.x;
    int n0 = blockIdx.x * 16;                      // 50000 = 3125*16
    for (int i = tid; i < 27 * 16; i += 256) {
        int k = i >> 4, m = i & 15;
        sxt[i] = x[(n0 + m) * 27 + k];
    }
    float w[27];
#pragma unroll
    for (int k = 0; k < 27; k++) w[k] = W1[k * 256 + tid];
    __syncthreads();
    ull acc[8];
#pragma unroll
    for (int p = 0; p < 8; p++) acc[p] = 0ull;
#pragma unroll
    for (int k = 0; k < 27; k++) {
        ull wp = pack2(w[k], w[k]);
        const ulonglong2* xp = (const ulonglong2*)(sxt + k * 16);
#pragma unroll
        for (int q = 0; q < 4; q++) {
            ulonglong2 xv = xp[q];
            acc[2 * q]     = fma2(xv.x, wp, acc[2 * q]);
            acc[2 * q + 1] = fma2(xv.y, wp, acc[2 * q + 1]);
        }
    }
#pragma unroll
    for (int p = 0; p < 8; p++) {
        float lo, hi; unpack2(acc[p], lo, hi);
        g_h1[(size_t)(n0 + 2 * p) * 256 + tid] = lo;
        g_h1[(size_t)(n0 + 2 * p + 1) * 256 + tid] = hi;
        sh1[(2 * p) * 256 + tid] = lo;
        sh1[(2 * p + 1) * 256 + tid] = hi;
    }
    __syncthreads();

    // scores: 8 warps x 2 nodes. lane handles cols lane*4.. (+3) and 128+lane*4..
    // head = (lane<16 ? 0 : 1) for first group, (lane<16 ? 2 : 3) for second.
    int wrp = tid >> 5, lane = tid & 31;
    const float4* aS = (const float4*)a_src1;
    const float4* aD = (const float4*)a_dst1;
    float4 sA = aS[lane], sB = aS[32 + lane];
    float4 dA = aD[lane], dB = aD[32 + lane];
#pragma unroll
    for (int mi = 0; mi < 2; mi++) {
        int m = wrp * 2 + mi;
        const float4* hr = (const float4*)(sh1 + m * 256);
        float4 hA = hr[lane];
        float4 hB = hr[32 + lane];
        float psA = hA.x * sA.x + hA.y * sA.y + hA.z * sA.z + hA.w * sA.w;
        float pdA = hA.x * dA.x + hA.y * dA.y + hA.z * dA.z + hA.w * dA.w;
        float psB = hB.x * sB.x + hB.y * sB.y + hB.z * sB.z + hB.w * sB.w;
        float pdB = hB.x * dB.x + hB.y * dB.y + hB.z * dB.z + hB.w * dB.w;
#pragma unroll
        for (int o = 8; o; o >>= 1) {      // reduce within 16-lane halves
            psA += __shfl_down_sync(0xFFFFFFFFu, psA, o);
            pdA += __shfl_down_sync(0xFFFFFFFFu, pdA, o);
            psB += __shfl_down_sync(0xFFFFFFFFu, psB, o);
            pdB += __shfl_down_sync(0xFFFFFFFFu, pdB, o);
        }
        int n = n0 + m;
        if (lane == 0) {                   // heads 0, 2
            g_ssrc1[n * 4 + 0] = psA; g_sdst1[n * 4 + 0] = pdA;
            g_ssrc1[n * 4 + 2] = psB; g_sdst1[n * 4 + 2] = pdB;
        }
        if (lane == 16) {                  // heads 1, 3
            g_ssrc1[n * 4 + 1] = psA; g_sdst1[n * 4 + 1] = pdA;
            g_ssrc1[n * 4 + 3] = psB; g_sdst1[n * 4 + 3] = pdB;
        }
    }
}

// ---------------- layer-1 aggregation: warp / dst, atomic-free ----------------
__global__ void __launch_bounds__(256) k_agg1(const float* __restrict__ b1) {
    __shared__ __align__(16) float4 s_w4[8][32];
    __shared__ int s_si[8][32];
    int wid = (blockIdx.x * blockDim.x + threadIdx.x) >> 5;
    if (wid >= NN) return;
    int wip = threadIdx.x >> 5;
    int lane = threadIdx.x & 31;
    int rs = g_rs[wid], re = g_rs[wid + 1];
    float4 sd = *(const float4*)(g_sdst1 + wid * 4);

    // pass 1: per-head max
    float4 mx = make_float4(-3.4e38f, -3.4e38f, -3.4e38f, -3.4e38f);
    for (int j = rs + lane; j < re; j += 32) {
        int s = g_csr[j];
        float4 ss = *(const float4*)(g_ssrc1 + s * 4);
        mx.x = fmaxf(mx.x, lrelu(ss.x + sd.x));
        mx.y = fmaxf(mx.y, lrelu(ss.y + sd.y));
        mx.z = fmaxf(mx.z, lrelu(ss.z + sd.z));
        mx.w = fmaxf(mx.w, lrelu(ss.w + sd.w));
    }
#pragma unroll
    for (int o = 16; o; o >>= 1) {
        mx.x = fmaxf(mx.x, __shfl_xor_sync(0xFFFFFFFFu, mx.x, o));
        mx.y = fmaxf(mx.y, __shfl_xor_sync(0xFFFFFFFFu, mx.y, o));
        mx.z = fmaxf(mx.z, __shfl_xor_sync(0xFFFFFFFFu, mx.z, o));
        mx.w = fmaxf(mx.w, __shfl_xor_sync(0xFFFFFFFFu, mx.w, o));
    }

    // pass 2: exp weights (staged in smem) + weighted gather-accumulate
    float4 zv = make_float4(0.f, 0.f, 0.f, 0.f);
    float4 accLo = make_float4(0.f, 0.f, 0.f, 0.f);
    float4 accHi = make_float4(0.f, 0.f, 0.f, 0.f);
    for (int base = rs; base < re; base += 32) {
        int cnt = min(32, re - base);
        int s_l = 0;
        float4 wv = make_float4(0.f, 0.f, 0.f, 0.f);
        if (lane < cnt) {
            s_l = g_csr[base + lane];
            float4 ss = *(const float4*)(g_ssrc1 + s_l * 4);
            wv.x = __expf(lrelu(ss.x + sd.x) - mx.x);
            wv.y = __expf(lrelu(ss.y + sd.y) - mx.y);
            wv.z = __expf(lrelu(ss.z + sd.z) - mx.z);
            wv.w = __expf(lrelu(ss.w + sd.w) - mx.w);
            zv.x += wv.x; zv.y += wv.y; zv.z += wv.z; zv.w += wv.w;
        }
        __syncwarp();
        s_w4[wip][lane] = wv;
        s_si[wip][lane] = s_l;
        __syncwarp();
        for (int t = 0; t < cnt; t++) {
            float4 w4 = s_w4[wip][t];
            int s = s_si[wip][t];
            const float4* hp = (const float4*)(g_h1 + (size_t)s * 256);
            float4 hLo = hp[lane];          // cols lane*4 .. +3     (heads 0/1)
            float4 hHi = hp[32 + lane];     // cols 128+lane*4 ..    (heads 2/3)
            float wa = (lane < 16) ? w4.x : w4.y;
            float wb = (lane < 16) ? w4.z : w4.w;
            accLo.x = fmaf(wa, hLo.x, accLo.x);
            accLo.y = fmaf(wa, hLo.y, accLo.y);
            accLo.z = fmaf(wa, hLo.z, accLo.z);
            accLo.w = fmaf(wa, hLo.w, accLo.w);
            accHi.x = fmaf(wb, hHi.x, accHi.x);
            accHi.y = fmaf(wb, hHi.y, accHi.y);
            accHi.z = fmaf(wb, hHi.z, accHi.z);
            accHi.w = fmaf(wb, hHi.w, accHi.w);
        }
    }
#pragma unroll
    for (int o = 16; o; o >>= 1) {
        zv.x += __shfl_xor_sync(0xFFFFFFFFu, zv.x, o);
        zv.y += __shfl_xor_sync(0xFFFFFFFFu, zv.y, o);
        zv.z += __shfl_xor_sync(0xFFFFFFFFu, zv.z, o);
        zv.w += __shfl_xor_sync(0xFFFFFFFFu, zv.w, o);
    }
    float ia = __fdividef(1.f, ((lane < 16) ? zv.x : zv.y) + EPS);
    float ib = __fdividef(1.f, ((lane < 16) ? zv.z : zv.w) + EPS);
    float4 bLo = *(const float4*)(b1 + lane * 4);
    float4 bHi = *(const float4*)(b1 + 128 + lane * 4);
    float4 v;
    v.x = elu(fmaf(accLo.x, ia, bLo.x));
    v.y = elu(fmaf(accLo.y, ia, bLo.y));
    v.z = elu(fmaf(accLo.z, ia, bLo.z));
    v.w = elu(fmaf(accLo.w, ia, bLo.w));
    *(float4*)(g_out1 + (size_t)wid * 256 + lane * 4) = v;
    v.x = elu(fmaf(accHi.x, ib, bHi.x));
    v.y = elu(fmaf(accHi.y, ib, bHi.y));
    v.z = elu(fmaf(accHi.z, ib, bHi.z));
    v.w = elu(fmaf(accHi.w, ib, bHi.w));
    *(float4*)(g_out1 + (size_t)wid * 256 + 128 + lane * 4) = v;
}

// ---------------- GEMM2 + scores2 fused ----------------
// [50000,256] @ [256,128] f32x2 packed, then per-node per-head half-scores
__global__ void __launch_bounds__(256) k_gemm2s(const float* __restrict__ W2,
                                                const float* __restrict__ a_src2,
                                                const float* __restrict__ a_dst2) {
    __shared__ __align__(16) float sxt[256 * 36];  // [k][m], stride 36 (pad)
    int tid = threadIdx.x;
    int n0 = blockIdx.x * 32;
    int cnt = min(32, NN - n0);
    if (cnt < 32) {
        for (int i = tid; i < 256 * 36; i += 256) sxt[i] = 0.f;
        __syncthreads();
    }
    for (int i = tid; i < cnt * 256; i += 256) {
        int m = i >> 8, k = i & 255;
        sxt[k * 36 + m] = g_out1[(size_t)(n0 + m) * 256 + k];
    }
    __syncthreads();
    int col = tid & 127;
    int g = tid >> 7;                              // node group: g*16 .. g*16+15
    ull acc[8];
#pragma unroll
    for (int p = 0; p < 8; p++) acc[p] = 0ull;
#pragma unroll 4
    for (int k = 0; k < 256; k++) {
        float wv = W2[k * 128 + col];
        ull wp = pack2(wv, wv);
        const ulonglong2* xp = (const ulonglong2*)(sxt + k * 36 + g * 16);
#pragma unroll
        for (int q = 0; q < 4; q++) {
            ulonglong2 xv = xp[q];
            acc[2 * q]     = fma2(xv.x, wp, acc[2 * q]);
            acc[2 * q + 1] = fma2(xv.y, wp, acc[2 * q + 1]);
        }
    }
    __syncthreads();                               // done reading sxt; reuse it
    float* sh2 = sxt;                              // [32][128] h2 tile
#pragma unroll
    for (int p = 0; p < 8; p++) {
        float lo, hi; unpack2(acc[p], lo, hi);
        int m = g * 16 + 2 * p;
        if (m < cnt)     g_h2[(size_t)(n0 + m) * 128 + col] = lo;
        if (m + 1 < cnt) g_h2[(size_t)(n0 + m + 1) * 128 + col] = hi;
        sh2[m * 128 + col] = lo;
        sh2[(m + 1) * 128 + col] = hi;
    }
    __syncthreads();

    // scores: 8 warps x 4 nodes. lane handles cols lane*4..+3.
    // head = lane<16 ? 0 : 1; reduce within 16-lane halves.
    int wrp = tid >> 5, lane = tid & 31;
    float4 sA = ((const float4*)a_src2)[lane];
    float4 dA = ((const float4*)a_dst2)[lane];
#pragma unroll
    for (int mi = 0; mi < 4; mi++) {
        int m = wrp * 4 + mi;
        float4 h = ((const float4*)(sh2 + m * 128))[lane];
        float ps = h.x * sA.x + h.y * sA.y + h.z * sA.z + h.w * sA.w;
        float pd = h.x * dA.x + h.y * dA.y + h.z * dA.z + h.w * dA.w;
#pragma unroll
        for (int o = 8; o; o >>= 1) {
            ps += __shfl_down_sync(0xFFFFFFFFu, ps, o);
            pd += __shfl_down_sync(0xFFFFFFFFu, pd, o);
        }
        int n = n0 + m;
        if (m < cnt) {
            if (lane == 0)  { g_ssrc2[n * 2 + 0] = ps; g_sdst2[n * 2 + 0] = pd; }
            if (lane == 16) { g_ssrc2[n * 2 + 1] = ps; g_sdst2[n * 2 + 1] = pd; }
        }
    }
}

// ---------------- layer-2 aggregation + FC + sigmoid, warp / dst -------------
// also re-zeroes g_deg / g_pub for the next replay
__global__ void __launch_bounds__(256) k_agg2(const float* __restrict__ b2,
                                              const float* __restrict__ Wfc,
                                              const float* __restrict__ bfc,
                                              float* __restrict__ out) {
    __shared__ __align__(8) float2 s_w2[8][32];
    __shared__ int s_si[8][32];
    int t0 = blockIdx.x * blockDim.x + threadIdx.x;
    if (t0 < NN) g_deg[t0] = 0;          // restore invariant for next call
    if (t0 < NBLK) g_pub[t0] = 0;

    int wid = t0 >> 5;
    if (wid >= NN) return;
    int wip = threadIdx.x >> 5;
    int lane = threadIdx.x & 31;
    int rs = g_rs[wid], re = g_rs[wid + 1];
    float2 sd = *(const float2*)(g_sdst2 + wid * 2);

    float2 mx = make_float2(-3.4e38f, -3.4e38f);
    for (int j = rs + lane; j < re; j += 32) {
        int s = g_csr[j];
        float2 ss = *(const float2*)(g_ssrc2 + s * 2);
        mx.x = fmaxf(mx.x, lrelu(ss.x + sd.x));
        mx.y = fmaxf(mx.y, lrelu(ss.y + sd.y));
    }
#pragma unroll
    for (int o = 16; o; o >>= 1) {
        mx.x = fmaxf(mx.x, __shfl_xor_sync(0xFFFFFFFFu, mx.x, o));
        mx.y = fmaxf(mx.y, __shfl_xor_sync(0xFFFFFFFFu, mx.y, o));
    }

    float2 zv = make_float2(0.f, 0.f);
    float4 acc = make_float4(0.f, 0.f, 0.f, 0.f);
    for (int base = rs; base < re; base += 32) {
        int cnt = min(32, re - base);
        int s_l = 0;
        float2 wv = make_float2(0.f, 0.f);
        if (lane < cnt) {
            s_l = g_csr[base + lane];
            float2 ss = *(const float2*)(g_ssrc2 + s_l * 2);
            wv.x = __expf(lrelu(ss.x + sd.x) - mx.x);
            wv.y = __expf(lrelu(ss.y + sd.y) - mx.y);
            zv.x += wv.x; zv.y += wv.y;
        }
        __syncwarp();
        s_w2[wip][lane] = wv;
        s_si[wip][lane] = s_l;
        __syncwarp();
        for (int t = 0; t < cnt; t++) {
            float2 w2 = s_w2[wip][t];
            int s = s_si[wip][t];
            const float4* hp = (const float4*)(g_h2 + (size_t)s * 128);
            float4 h = hp[lane];            // cols lane*4 .. +3
            float wa = (lane < 16) ? w2.x : w2.y;
            acc.x = fmaf(wa, h.x, acc.x);
            acc.y = fmaf(wa, h.y, acc.y);
            acc.z = fmaf(wa, h.z, acc.z);
            acc.w = fmaf(wa, h.w, acc.w);
        }
    }
#pragma unroll
    for (int o = 16; o; o >>= 1) {
        zv.x += __shfl_xor_sync(0xFFFFFFFFu, zv.x, o);
        zv.y += __shfl_xor_sync(0xFFFFFFFFu, zv.y, o);
    }
    float iz = __fdividef(1.f, ((lane < 16) ? zv.x : zv.y) + EPS);
    float4 b = *(const float4*)(b2 + lane * 4);
    float4 wf = *(const float4*)(Wfc + lane * 4);
    float t = elu(fmaf(acc.x, iz, b.x)) * wf.x
            + elu(fmaf(acc.y, iz, b.y)) * wf.y
            + elu(fmaf(acc.z, iz, b.z)) * wf.z
            + elu(fmaf(acc.w, iz, b.w)) * wf.w;
#pragma unroll
    for (int o = 16; o; o >>= 1) t += __shfl_down_sync(0xFFFFFFFFu, t, o);
    if (lane == 0) {
        float s = t + bfc[0];
        out[wid] = __fdividef(1.f, 1.f + __expf(-s));
    }
}

// ---------------- launch ----------------
extern "C" void kernel_launch(void* const* d_in, const int* in_sizes, int n_in,
                              void* d_out, int out_size) {
    const float* x      = (const float*)d_in[0];
    const void*  ei     = d_in[1];
    const float* W1     = (const float*)d_in[2];
    const float* a_src1 = (const float*)d_in[3];
    const float* a_dst1 = (const float*)d_in[4];
    const float* b1     = (const float*)d_in[5];
    const float* W2     = (const float*)d_in[6];
    const float* a_src2 = (const float*)d_in[7];
    const float* a_dst2 = (const float*)d_in[8];
    const float* b2     = (const float*)d_in[9];
    const float* Wfc    = (const float*)d_in[10];
    const float* bfc    = (const float*)d_in[11];
    float* out = (float*)d_out;

    k_convert<<<(ETOT + 255) / 256, 256>>>(ei);        // 0
    k_scan<<<NBLK, SCAN_B>>>();                        // 1
    k_scatter<<<(ETOT + 255) / 256, 256>>>();          // 2
    k_gemm1s<<<NN / 16, 256>>>(x, W1, a_src1, a_dst1); // 3  <- ncu profiles this
    k_agg1<<<(NN + 7) / 8, 256>>>(b1);                 // 4
    k_gemm2s<<<(NN + 31) / 32, 256>>>(W2, a_src2, a_dst2); // 5
    k_agg2<<<(NN + 7) / 8, 256>>>(b2, Wfc, bfc, out);  // 6
}